// round 13
// baseline (speedup 1.0000x reference)
#include <cuda_runtime.h>
#include <math.h>
#include <stdint.h>

#define SEQ   2048
#define DIM   4096
#define NH    32
#define NKV   8
#define HD    128
#define KVDIM (NKV*HD)   /* 1024 */

// ---------------- scratch (no allocations allowed) ----------------
__device__ float  g_Q[SEQ*DIM];
__device__ float  g_K[SEQ*KVDIM];
__device__ float  g_V[SEQ*KVDIM];
__device__ float  g_A[SEQ*DIM];
__device__ float2 g_cs[SEQ*64];     // RoPE cos/sin table

// =================================================================
// portable PTX helpers (family-safe: compiles under compute_103)
// =================================================================
__device__ __forceinline__ uint32_t s2u(const void* p) {
    uint32_t a;
    asm("{ .reg .u64 t; cvta.to.shared.u64 t, %1; cvt.u32.u64 %0, t; }"
        : "=r"(a) : "l"(p));
    return a;
}
__device__ __forceinline__ void cp16(uint32_t dst, const void* src) {
    asm volatile("cp.async.cg.shared.global [%0], [%1], 16;"
                 :: "r"(dst), "l"(src) : "memory");
}
__device__ __forceinline__ void cp_commit() {
    asm volatile("cp.async.commit_group;" ::: "memory");
}
template <int N>
__device__ __forceinline__ void cp_wait() {
    asm volatile("cp.async.wait_group %0;" :: "n"(N) : "memory");
}
// D += A*B  (m16n8k8, tf32 inputs, fp32 accum)
__device__ __forceinline__ void mma_tf32(float* c, const uint32_t* a, const uint32_t* b) {
    asm volatile(
        "mma.sync.aligned.m16n8k8.row.col.f32.tf32.tf32.f32 "
        "{%0,%1,%2,%3}, {%4,%5,%6,%7}, {%8,%9}, {%0,%1,%2,%3};"
        : "+f"(c[0]), "+f"(c[1]), "+f"(c[2]), "+f"(c[3])
        : "r"(a[0]), "r"(a[1]), "r"(a[2]), "r"(a[3]), "r"(b[0]), "r"(b[1]));
}
// v -> (hi, lo): mask-based tf32 split (fast ALU, no F2F cvt).
__device__ __forceinline__ void split_tf32(float v, uint32_t& hi, uint32_t& lo) {
    const uint32_t hb = __float_as_uint(v) & 0xFFFFE000u;
    const float lf = v - __uint_as_float(hb);
    hi = hb;
    lo = __float_as_uint(lf) & 0xFFFFE000u;
}

// =================================================================
// 3xTF32 GEMM core: C[.,N] = A[.,K] * B[N,K]^T (row-major, K contig)
// 128x128 CTA tile, BK=32, 512 threads (16 warps 4x4), warp tile 32x32.
// cp.async double-buffered raw fp32; mask-split at fragment load;
// pass-major MMA order (lo*hi, hi*lo, hi*hi).
// =================================================================
#define GST 36                                  /* smem row stride (floats) */
#define GBUF (128 * GST)                        /* one tile: 4608 floats */
#define G_SMEM (4 * GBUF * (int)sizeof(float))  /* 2 bufs x (A+B) = 73728 B */

__device__ __forceinline__ void gemm_core(
    const float* __restrict__ A, const float* __restrict__ B,
    float* __restrict__ C, int N, int K, int bm, int bn, float* sm)
{
    const uint32_t sb = s2u(sm);
    const int tid = threadIdx.x;
    const int wid = tid >> 5, lane = tid & 31;
    const int g = lane >> 2, tig = lane & 3;
    const int warp_m = wid >> 2, warp_n = wid & 3;

    auto load_chunk = [&](int kc, int buf) {
        const float* Ap = A + (size_t)bm * K + kc * 32;
        const float* Bp = B + (size_t)bn * K + kc * 32;
        const uint32_t ab = sb + (uint32_t)(2 * buf)     * GBUF * 4;
        const uint32_t bb = sb + (uint32_t)(2 * buf + 1) * GBUF * 4;
#pragma unroll
        for (int t = 0; t < 2; t++) {
            int i = tid + t * 512;              // 0..1023 float4 slots
            int r = i >> 3, c = (i & 7) * 4;
            uint32_t so = (uint32_t)(r * GST + c) * 4;
            cp16(ab + so, Ap + (size_t)r * K + c);
            cp16(bb + so, Bp + (size_t)r * K + c);
        }
        cp_commit();
    };

    float acc[2][4][4];
#pragma unroll
    for (int i = 0; i < 2; i++)
#pragma unroll
        for (int j = 0; j < 4; j++)
#pragma unroll
            for (int q = 0; q < 4; q++) acc[i][j][q] = 0.f;

    const int NC = K >> 5;
    load_chunk(0, 0);

    for (int kc = 0; kc < NC; kc++) {
        if (kc + 1 < NC) { load_chunk(kc + 1, (kc + 1) & 1); cp_wait<1>(); }
        else             { cp_wait<0>(); }
        __syncthreads();

        const float* As = sm + (2 * (kc & 1))     * GBUF;
        const float* Bs = sm + (2 * (kc & 1) + 1) * GBUF;

#pragma unroll
        for (int ks = 0; ks < 4; ks++) {
            const int k0 = ks * 8;
            uint32_t ah[2][4], al[2][4], bh[4][2], bl[4][2];
#pragma unroll
            for (int tm = 0; tm < 2; tm++) {
                const int r0 = warp_m * 32 + tm * 16 + g;
                split_tf32(As[ r0      * GST + k0 + tig    ], ah[tm][0], al[tm][0]);
                split_tf32(As[(r0 + 8) * GST + k0 + tig    ], ah[tm][1], al[tm][1]);
                split_tf32(As[ r0      * GST + k0 + tig + 4], ah[tm][2], al[tm][2]);
                split_tf32(As[(r0 + 8) * GST + k0 + tig + 4], ah[tm][3], al[tm][3]);
            }
#pragma unroll
            for (int tn = 0; tn < 4; tn++) {
                const int r0 = warp_n * 32 + tn * 8 + g;
                split_tf32(Bs[r0 * GST + k0 + tig    ], bh[tn][0], bl[tn][0]);
                split_tf32(Bs[r0 * GST + k0 + tig + 4], bh[tn][1], bl[tn][1]);
            }
            // pass-major order: long dependency distance on each accumulator
#pragma unroll
            for (int tm = 0; tm < 2; tm++)
#pragma unroll
                for (int tn = 0; tn < 4; tn++)
                    mma_tf32(acc[tm][tn], al[tm], bh[tn]);
#pragma unroll
            for (int tm = 0; tm < 2; tm++)
#pragma unroll
                for (int tn = 0; tn < 4; tn++)
                    mma_tf32(acc[tm][tn], ah[tm], bl[tn]);
#pragma unroll
            for (int tm = 0; tm < 2; tm++)
#pragma unroll
                for (int tn = 0; tn < 4; tn++)
                    mma_tf32(acc[tm][tn], ah[tm], bh[tn]);
        }
        __syncthreads();
    }

    // ---- epilogue ----
#pragma unroll
    for (int tm = 0; tm < 2; tm++) {
        const int row = bm + warp_m * 32 + tm * 16 + g;
#pragma unroll
        for (int tn = 0; tn < 4; tn++) {
            const int col = bn + warp_n * 32 + tn * 8 + tig * 2;
            *(float2*)&C[(size_t) row      * N + col] =
                make_float2(acc[tm][tn][0], acc[tm][tn][1]);
            *(float2*)&C[(size_t)(row + 8) * N + col] =
                make_float2(acc[tm][tn][2], acc[tm][tn][3]);
        }
    }
}

// Fused QKV projection: bx 0..31 -> Q, 32..39 -> K, 40..47 -> V
__global__ __launch_bounds__(512, 1)
void gemm_qkv(const float* __restrict__ x, const float* __restrict__ wq,
              const float* __restrict__ wk, const float* __restrict__ wv)
{
    extern __shared__ float sm[];
    const int bx = blockIdx.x;
    const int bm = blockIdx.y * 128;
    const float* B; float* C; int N, bn;
    if (bx < 32)      { B = wq; C = g_Q; N = DIM;   bn = bx * 128; }
    else if (bx < 40) { B = wk; C = g_K; N = KVDIM; bn = (bx - 32) * 128; }
    else              { B = wv; C = g_V; N = KVDIM; bn = (bx - 40) * 128; }
    gemm_core(x, B, C, N, DIM, bm, bn, sm);
}

__global__ __launch_bounds__(512, 1)
void gemm_nt(const float* __restrict__ A, const float* __restrict__ B,
             float* __restrict__ C, int N, int K)
{
    extern __shared__ float sm[];
    gemm_core(A, B, C, N, K, blockIdx.y * 128, blockIdx.x * 128, sm);
}

// =================================================================
// RoPE: precompute (cos,sin) table once (double precision), then a
// trivial memory-bound apply (Q and K fused into one launch).
// =================================================================
__global__ void rope_table()
{
    int idx = blockIdx.x * blockDim.x + threadIdx.x;
    if (idx >= SEQ * 64) return;
    const int t = idx >> 6, i = idx & 63;
    const double ang = (double)t * pow(500000.0, -(double)i / 64.0);
    g_cs[idx] = make_float2((float)cos(ang), (float)sin(ang));
}

#define ROPE_TOTQ (SEQ * NH  * 64)
#define ROPE_TOTK (SEQ * NKV * 64)

__global__ void rope_apply(float* __restrict__ Xq, float* __restrict__ Xk)
{
    int idx = blockIdx.x * blockDim.x + threadIdx.x;
    float* X; int n_heads;
    if (idx < ROPE_TOTQ) { X = Xq; n_heads = NH; }
    else {
        idx -= ROPE_TOTQ;
        if (idx >= ROPE_TOTK) return;
        X = Xk; n_heads = NKV;
    }
    const int i    = idx & 63;
    const int rest = idx >> 6;
    const int h    = rest % n_heads;
    const int t    = rest / n_heads;

    const float2 cs = g_cs[(t << 6) | i];
    float2* p = (float2*)(X + (((size_t)t * n_heads + h) << 7) + 2 * i);
    const float2 v = *p;
    *p = make_float2(v.x * cs.x - v.y * cs.y, v.x * cs.y + v.y * cs.x);
}

// =================================================================
// Flash attention (causal, GQA 4:1), fp32 SIMT — R6-proven.
// =================================================================
#define BQ  64
#define BKT 64
#define PSTRIDE 68

__device__ __forceinline__ int kswz(int r, int g) {
    return r * HD + ((g ^ ((r >> 2) & 7)) << 2);
}

__global__ __launch_bounds__(256, 1)
void flash_kernel(const float* __restrict__ Q, const float* __restrict__ K,
                  const float* __restrict__ V, float* __restrict__ O)
{
    extern __shared__ float sm[];
    float* Qs = sm;
    float* Ks = Qs + BQ  * HD;
    float* Vs = Ks + BKT * HD;
    float* Ps = Vs + BKT * HD;

    const int qb  = blockIdx.x;
    const int h   = blockIdx.y;
    const int kvh = h >> 2;
    const int tid = threadIdx.x;
    const int tx  = tid & 15;
    const int ty  = tid >> 4;

    const float* Qg = Q + (size_t)qb * BQ * DIM + h * HD;
#pragma unroll
    for (int it = 0; it < 8; it++) {
        int i = tid + it * 256;
        int r = i >> 5, g = i & 31;
        *(float4*)&Qs[r * HD + g * 4] =
            *(const float4*)(Qg + (size_t)r * DIM + g * 4);
    }

    float m[4], l[4], acc[4][8];
#pragma unroll
    for (int i = 0; i < 4; i++) {
        m[i] = -1e30f; l[i] = 0.f;
#pragma unroll
        for (int j = 0; j < 8; j++) acc[i][j] = 0.f;
    }
    const float scale = 0.08838834764831845f;

    for (int kb = 0; kb <= qb; kb++) {
        __syncthreads();

        const float* Kg = K + (size_t)kb * BKT * KVDIM + kvh * HD;
        const float* Vg = V + (size_t)kb * BKT * KVDIM + kvh * HD;
#pragma unroll
        for (int it = 0; it < 8; it++) {
            int i = tid + it * 256;
            int r = i >> 5, g = i & 31;
            *(float4*)&Ks[kswz(r, g)]     = *(const float4*)(Kg + (size_t)r * KVDIM + g * 4);
            *(float4*)&Vs[r * HD + g * 4] = *(const float4*)(Vg + (size_t)r * KVDIM + g * 4);
        }
        __syncthreads();

        float s[4][4];
#pragma unroll
        for (int i = 0; i < 4; i++)
#pragma unroll
            for (int j = 0; j < 4; j++) s[i][j] = 0.f;

#pragma unroll 8
        for (int g = 0; g < 32; g++) {
            float4 q0 = *(const float4*)&Qs[(ty*4+0) * HD + g*4];
            float4 q1 = *(const float4*)&Qs[(ty*4+1) * HD + g*4];
            float4 q2 = *(const float4*)&Qs[(ty*4+2) * HD + g*4];
            float4 q3 = *(const float4*)&Qs[(ty*4+3) * HD + g*4];
            float4 k0 = *(const float4*)&Ks[kswz(tx*4+0, g)];
            float4 k1 = *(const float4*)&Ks[kswz(tx*4+1, g)];
            float4 k2 = *(const float4*)&Ks[kswz(tx*4+2, g)];
            float4 k3 = *(const float4*)&Ks[kswz(tx*4+3, g)];
            float4 qv[4] = {q0, q1, q2, q3};
            float4 kv[4] = {k0, k1, k2, k3};
#pragma unroll
            for (int i = 0; i < 4; i++)
#pragma unroll
                for (int j = 0; j < 4; j++)
                    s[i][j] += qv[i].x*kv[j].x + qv[i].y*kv[j].y
                             + qv[i].z*kv[j].z + qv[i].w*kv[j].w;
        }

#pragma unroll
        for (int i = 0; i < 4; i++)
#pragma unroll
            for (int j = 0; j < 4; j++) s[i][j] *= scale;
        if (kb == qb) {
#pragma unroll
            for (int i = 0; i < 4; i++)
#pragma unroll
                for (int j = 0; j < 4; j++)
                    if (tx*4 + j > ty*4 + i) s[i][j] = -1e30f;
        }

#pragma unroll
        for (int i = 0; i < 4; i++) {
            float rm = fmaxf(fmaxf(s[i][0], s[i][1]), fmaxf(s[i][2], s[i][3]));
#pragma unroll
            for (int o = 8; o > 0; o >>= 1)
                rm = fmaxf(rm, __shfl_xor_sync(0xffffffffu, rm, o, 16));
            const float mn    = fmaxf(m[i], rm);
            const float alpha = __expf(m[i] - mn);
            float rs = 0.f;
#pragma unroll
            for (int j = 0; j < 4; j++) { s[i][j] = __expf(s[i][j] - mn); rs += s[i][j]; }
#pragma unroll
            for (int o = 8; o > 0; o >>= 1)
                rs += __shfl_xor_sync(0xffffffffu, rs, o, 16);
            l[i] = l[i] * alpha + rs;
            m[i] = mn;
#pragma unroll
            for (int j = 0; j < 8; j++) acc[i][j] *= alpha;
#pragma unroll
            for (int j = 0; j < 4; j++)
                Ps[(ty*4 + i) * PSTRIDE + tx*4 + j] = s[i][j];
        }
        __syncthreads();

#pragma unroll 4
        for (int kk = 0; kk < BKT; kk++) {
            float p[4];
#pragma unroll
            for (int i = 0; i < 4; i++) p[i] = Ps[(ty*4 + i) * PSTRIDE + kk];
            float4 v0 = *(const float4*)&Vs[kk * HD + tx*8];
            float4 v1 = *(const float4*)&Vs[kk * HD + tx*8 + 4];
#pragma unroll
            for (int i = 0; i < 4; i++) {
                acc[i][0] += p[i]*v0.x; acc[i][1] += p[i]*v0.y;
                acc[i][2] += p[i]*v0.z; acc[i][3] += p[i]*v0.w;
                acc[i][4] += p[i]*v1.x; acc[i][5] += p[i]*v1.y;
                acc[i][6] += p[i]*v1.z; acc[i][7] += p[i]*v1.w;
            }
        }
    }

#pragma unroll
    for (int i = 0; i < 4; i++) {
        const float inv = 1.0f / l[i];
        const int row = qb * BQ + ty*4 + i;
        float* Op = O + (size_t)row * DIM + h * HD + tx*8;
        float4 o0, o1;
        o0.x = acc[i][0]*inv; o0.y = acc[i][1]*inv;
        o0.z = acc[i][2]*inv; o0.w = acc[i][3]*inv;
        o1.x = acc[i][4]*inv; o1.y = acc[i][5]*inv;
        o1.z = acc[i][6]*inv; o1.w = acc[i][7]*inv;
        *(float4*)Op       = o0;
        *(float4*)(Op + 4) = o1;
    }
}

// =================================================================
// launch
// =================================================================
#define FLASH_SMEM ((3 * BQ * HD + BQ * PSTRIDE) * (int)sizeof(float))

extern "C" void kernel_launch(void* const* d_in, const int* in_sizes, int n_in,
                              void* d_out, int out_size)
{
    const float* x  = (const float*)d_in[0];
    const float* wq = (const float*)d_in[1];
    const float* wk = (const float*)d_in[2];
    const float* wv = (const float*)d_in[3];
    const float* wo = (const float*)d_in[4];
    float* out = (float*)d_out;

    float *Q, *K, *V, *A;
    cudaGetSymbolAddress((void**)&Q, g_Q);
    cudaGetSymbolAddress((void**)&K, g_K);
    cudaGetSymbolAddress((void**)&V, g_V);
    cudaGetSymbolAddress((void**)&A, g_A);

    cudaFuncSetAttribute(gemm_qkv,
                         cudaFuncAttributeMaxDynamicSharedMemorySize, G_SMEM);
    cudaFuncSetAttribute(gemm_nt,
                         cudaFuncAttributeMaxDynamicSharedMemorySize, G_SMEM);
    cudaFuncSetAttribute(flash_kernel,
                         cudaFuncAttributeMaxDynamicSharedMemorySize, FLASH_SMEM);

    // RoPE table (independent of projections)
    rope_table<<<(SEQ * 64 + 255) / 256, 256>>>();

    // fused Q/K/V projections (3xTF32 mma.sync, 16 warps/CTA)
    gemm_qkv<<<dim3(48, SEQ/128), 512, G_SMEM>>>(x, wq, wk, wv);

    // RoPE apply (Q + K fused)
    rope_apply<<<(ROPE_TOTQ + ROPE_TOTK + 255) / 256, 256>>>(Q, K);

    // attention
    flash_kernel<<<dim3(SEQ/BQ, NH), 256, FLASH_SMEM>>>(Q, K, V, A);

    // output projection
    gemm_nt<<<dim3(DIM/128, SEQ/128), 512, G_SMEM>>>(A, wo, out, DIM, DIM);
}

// round 14
// speedup vs baseline: 1.0754x; 1.0754x over previous
#include <cuda_runtime.h>
#include <math.h>
#include <stdint.h>

#define SEQ   2048
#define DIM   4096
#define NH    32
#define NKV   8
#define HD    128
#define KVDIM (NKV*HD)   /* 1024 */

// ---------------- scratch (no allocations allowed) ----------------
__device__ float  g_Q[SEQ*DIM];
__device__ float  g_K[SEQ*KVDIM];
__device__ float  g_V[SEQ*KVDIM];
__device__ float  g_A[SEQ*DIM];
__device__ float2 g_cs[SEQ*64];     // RoPE cos/sin table

// =================================================================
// portable PTX helpers (family-safe: compiles under compute_103)
// =================================================================
__device__ __forceinline__ uint32_t s2u(const void* p) {
    uint32_t a;
    asm("{ .reg .u64 t; cvta.to.shared.u64 t, %1; cvt.u32.u64 %0, t; }"
        : "=r"(a) : "l"(p));
    return a;
}
__device__ __forceinline__ void cp16(uint32_t dst, const void* src) {
    asm volatile("cp.async.cg.shared.global [%0], [%1], 16;"
                 :: "r"(dst), "l"(src) : "memory");
}
__device__ __forceinline__ void cp_commit() {
    asm volatile("cp.async.commit_group;" ::: "memory");
}
template <int N>
__device__ __forceinline__ void cp_wait() {
    asm volatile("cp.async.wait_group %0;" :: "n"(N) : "memory");
}
// D += A*B  (m16n8k8, tf32 inputs, fp32 accum)
__device__ __forceinline__ void mma_tf32(float* c, const uint32_t* a, const uint32_t* b) {
    asm volatile(
        "mma.sync.aligned.m16n8k8.row.col.f32.tf32.tf32.f32 "
        "{%0,%1,%2,%3}, {%4,%5,%6,%7}, {%8,%9}, {%0,%1,%2,%3};"
        : "+f"(c[0]), "+f"(c[1]), "+f"(c[2]), "+f"(c[3])
        : "r"(a[0]), "r"(a[1]), "r"(a[2]), "r"(a[3]), "r"(b[0]), "r"(b[1]));
}
// v -> (hi, lo): mask-based tf32 split (fast ALU, no F2F cvt).
__device__ __forceinline__ void split_tf32(float v, uint32_t& hi, uint32_t& lo) {
    const uint32_t hb = __float_as_uint(v) & 0xFFFFE000u;
    const float lf = v - __uint_as_float(hb);
    hi = hb;
    lo = __float_as_uint(lf) & 0xFFFFE000u;
}

// =================================================================
// 3xTF32 GEMM core (R12-proven shape): 128x128 CTA tile, BK=32,
// 256 threads (8 warps 2x4), warp tile 64x32, double-buffered cp.async.
// =================================================================
#define GST 36                                  /* smem row stride (floats) */
#define GBUF (128 * GST)                        /* one tile: 4608 floats */
#define G_SMEM (4 * GBUF * (int)sizeof(float))  /* 2 bufs x (A+B) = 73728 B */

__device__ __forceinline__ void gemm_core(
    const float* __restrict__ A, const float* __restrict__ B,
    float* __restrict__ C, int N, int K, int bm, int bn, float* sm)
{
    const uint32_t sb = s2u(sm);
    const int tid = threadIdx.x;
    const int wid = tid >> 5, lane = tid & 31;
    const int g = lane >> 2, tig = lane & 3;
    const int warp_m = wid >> 2, warp_n = wid & 3;

    auto load_chunk = [&](int kc, int buf) {
        const float* Ap = A + (size_t)bm * K + kc * 32;
        const float* Bp = B + (size_t)bn * K + kc * 32;
        const uint32_t ab = sb + (uint32_t)(2 * buf)     * GBUF * 4;
        const uint32_t bb = sb + (uint32_t)(2 * buf + 1) * GBUF * 4;
#pragma unroll
        for (int t = 0; t < 4; t++) {
            int i = tid + t * 256;
            int r = i >> 3, c = (i & 7) * 4;
            uint32_t so = (uint32_t)(r * GST + c) * 4;
            cp16(ab + so, Ap + (size_t)r * K + c);
            cp16(bb + so, Bp + (size_t)r * K + c);
        }
        cp_commit();
    };

    float acc[4][4][4];
#pragma unroll
    for (int i = 0; i < 4; i++)
#pragma unroll
        for (int j = 0; j < 4; j++)
#pragma unroll
            for (int q = 0; q < 4; q++) acc[i][j][q] = 0.f;

    const int NC = K >> 5;
    load_chunk(0, 0);

    for (int kc = 0; kc < NC; kc++) {
        if (kc + 1 < NC) { load_chunk(kc + 1, (kc + 1) & 1); cp_wait<1>(); }
        else             { cp_wait<0>(); }
        __syncthreads();

        const float* As = sm + (2 * (kc & 1))     * GBUF;
        const float* Bs = sm + (2 * (kc & 1) + 1) * GBUF;

#pragma unroll
        for (int ks = 0; ks < 4; ks++) {
            const int k0 = ks * 8;
            uint32_t ah[4][4], al[4][4], bh[4][2], bl[4][2];
#pragma unroll
            for (int tm = 0; tm < 4; tm++) {
                const int r0 = warp_m * 64 + tm * 16 + g;
                split_tf32(As[ r0      * GST + k0 + tig    ], ah[tm][0], al[tm][0]);
                split_tf32(As[(r0 + 8) * GST + k0 + tig    ], ah[tm][1], al[tm][1]);
                split_tf32(As[ r0      * GST + k0 + tig + 4], ah[tm][2], al[tm][2]);
                split_tf32(As[(r0 + 8) * GST + k0 + tig + 4], ah[tm][3], al[tm][3]);
            }
#pragma unroll
            for (int tn = 0; tn < 4; tn++) {
                const int r0 = warp_n * 32 + tn * 8 + g;
                split_tf32(Bs[r0 * GST + k0 + tig    ], bh[tn][0], bl[tn][0]);
                split_tf32(Bs[r0 * GST + k0 + tig + 4], bh[tn][1], bl[tn][1]);
            }
            // pass-major order: long dependency distance on each accumulator
#pragma unroll
            for (int tm = 0; tm < 4; tm++)
#pragma unroll
                for (int tn = 0; tn < 4; tn++)
                    mma_tf32(acc[tm][tn], al[tm], bh[tn]);
#pragma unroll
            for (int tm = 0; tm < 4; tm++)
#pragma unroll
                for (int tn = 0; tn < 4; tn++)
                    mma_tf32(acc[tm][tn], ah[tm], bl[tn]);
#pragma unroll
            for (int tm = 0; tm < 4; tm++)
#pragma unroll
                for (int tn = 0; tn < 4; tn++)
                    mma_tf32(acc[tm][tn], ah[tm], bh[tn]);
        }
        __syncthreads();
    }

#pragma unroll
    for (int tm = 0; tm < 4; tm++) {
        const int row = bm + warp_m * 64 + tm * 16 + g;
#pragma unroll
        for (int tn = 0; tn < 4; tn++) {
            const int col = bn + warp_n * 32 + tn * 8 + tig * 2;
            *(float2*)&C[(size_t) row      * N + col] =
                make_float2(acc[tm][tn][0], acc[tm][tn][1]);
            *(float2*)&C[(size_t)(row + 8) * N + col] =
                make_float2(acc[tm][tn][2], acc[tm][tn][3]);
        }
    }
}

// Fused QKV projection: bx 0..31 -> Q, 32..39 -> K, 40..47 -> V
__global__ __launch_bounds__(256, 1)
void gemm_qkv(const float* __restrict__ x, const float* __restrict__ wq,
              const float* __restrict__ wk, const float* __restrict__ wv)
{
    extern __shared__ float sm[];
    const int bx = blockIdx.x;
    const int bm = blockIdx.y * 128;
    const float* B; float* C; int N, bn;
    if (bx < 32)      { B = wq; C = g_Q; N = DIM;   bn = bx * 128; }
    else if (bx < 40) { B = wk; C = g_K; N = KVDIM; bn = (bx - 32) * 128; }
    else              { B = wv; C = g_V; N = KVDIM; bn = (bx - 40) * 128; }
    gemm_core(x, B, C, N, DIM, bm, bn, sm);
}

__global__ __launch_bounds__(256, 1)
void gemm_nt(const float* __restrict__ A, const float* __restrict__ B,
             float* __restrict__ C, int N, int K)
{
    extern __shared__ float sm[];
    gemm_core(A, B, C, N, K, blockIdx.y * 128, blockIdx.x * 128, sm);
}

// =================================================================
// RoPE: table once (double precision) + memory-bound apply (fused Q/K).
// =================================================================
__global__ void rope_table()
{
    int idx = blockIdx.x * blockDim.x + threadIdx.x;
    if (idx >= SEQ * 64) return;
    const int t = idx >> 6, i = idx & 63;
    const double ang = (double)t * pow(500000.0, -(double)i / 64.0);
    g_cs[idx] = make_float2((float)cos(ang), (float)sin(ang));
}

#define ROPE_TOTQ (SEQ * NH  * 64)
#define ROPE_TOTK (SEQ * NKV * 64)

__global__ void rope_apply(float* __restrict__ Xq, float* __restrict__ Xk)
{
    int idx = blockIdx.x * blockDim.x + threadIdx.x;
    float* X; int n_heads;
    if (idx < ROPE_TOTQ) { X = Xq; n_heads = NH; }
    else {
        idx -= ROPE_TOTQ;
        if (idx >= ROPE_TOTK) return;
        X = Xk; n_heads = NKV;
    }
    const int i    = idx & 63;
    const int rest = idx >> 6;
    const int h    = rest % n_heads;
    const int t    = rest / n_heads;

    const float2 cs = g_cs[(t << 6) | i];
    float2* p = (float2*)(X + (((size_t)t * n_heads + h) << 7) + 2 * i);
    const float2 v = *p;
    *p = make_float2(v.x * cs.x - v.y * cs.y, v.x * cs.y + v.y * cs.x);
}

// =================================================================
// Flash attention (causal, GQA 4:1), fp32 SIMT.
// BQ=128 (doubled), BKT=64: halves K/V smem+global traffic per work.
// 256 threads: tx 0..15 (4 S-cols), ty 0..15 (8 S-rows, 8 O-cols x8).
// =================================================================
#define BQ  128
#define BKT 64
#define PSTRIDE 68

__device__ __forceinline__ int kswz(int r, int g) {
    return r * HD + ((g ^ ((r >> 2) & 7)) << 2);
}

__global__ __launch_bounds__(256, 1)
void flash_kernel(const float* __restrict__ Q, const float* __restrict__ K,
                  const float* __restrict__ V, float* __restrict__ O)
{
    extern __shared__ float sm[];
    float* Qs = sm;                   // [128][128]
    float* Ks = Qs + BQ  * HD;        // [64][128] swizzled
    float* Vs = Ks + BKT * HD;        // [64][128]
    float* Ps = Vs + BKT * HD;        // [128][68]

    const int qb  = blockIdx.x;       // q block of 128 rows
    const int h   = blockIdx.y;
    const int kvh = h >> 2;
    const int tid = threadIdx.x;
    const int tx  = tid & 15;
    const int ty  = tid >> 4;

    // ---- load Q tile (once): 128x128 ----
    const float* Qg = Q + (size_t)qb * BQ * DIM + h * HD;
#pragma unroll
    for (int it = 0; it < 16; it++) {
        int i = tid + it * 256;
        int r = i >> 5, g = i & 31;
        *(float4*)&Qs[r * HD + g * 4] =
            *(const float4*)(Qg + (size_t)r * DIM + g * 4);
    }

    float m[8], l[8], acc[8][8];
#pragma unroll
    for (int i = 0; i < 8; i++) {
        m[i] = -1e30f; l[i] = 0.f;
#pragma unroll
        for (int j = 0; j < 8; j++) acc[i][j] = 0.f;
    }
    const float scale = 0.08838834764831845f;  // 1/sqrt(128)

    const int nkb = 2 * qb + 2;       // 64-col blocks up to and incl. diagonal
    for (int kb = 0; kb < nkb; kb++) {
        __syncthreads();

        const float* Kg = K + (size_t)kb * BKT * KVDIM + kvh * HD;
        const float* Vg = V + (size_t)kb * BKT * KVDIM + kvh * HD;
#pragma unroll
        for (int it = 0; it < 8; it++) {
            int i = tid + it * 256;
            int r = i >> 5, g = i & 31;
            *(float4*)&Ks[kswz(r, g)]     = *(const float4*)(Kg + (size_t)r * KVDIM + g * 4);
            *(float4*)&Vs[r * HD + g * 4] = *(const float4*)(Vg + (size_t)r * KVDIM + g * 4);
        }
        __syncthreads();

        // ---- S = Q K^T (8x4 per thread) ----
        float s[8][4];
#pragma unroll
        for (int i = 0; i < 8; i++)
#pragma unroll
            for (int j = 0; j < 4; j++) s[i][j] = 0.f;

#pragma unroll 4
        for (int g = 0; g < 32; g++) {
            float4 kv[4];
#pragma unroll
            for (int j = 0; j < 4; j++)
                kv[j] = *(const float4*)&Ks[kswz(tx*4 + j, g)];
#pragma unroll
            for (int i = 0; i < 8; i++) {
                float4 qv = *(const float4*)&Qs[(ty*8 + i) * HD + g*4];
#pragma unroll
                for (int j = 0; j < 4; j++)
                    s[i][j] += qv.x*kv[j].x + qv.y*kv[j].y
                             + qv.z*kv[j].z + qv.w*kv[j].w;
            }
        }

        // ---- scale + causal mask (exact global-index compare) ----
        const bool diag = (kb >= 2 * qb);   // only last two blocks partial
#pragma unroll
        for (int i = 0; i < 8; i++)
#pragma unroll
            for (int j = 0; j < 4; j++) s[i][j] *= scale;
        if (diag) {
            const int roff = qb * BQ + ty * 8;     // global q row base
            const int coff = kb * BKT + tx * 4;    // global k col base
#pragma unroll
            for (int i = 0; i < 8; i++)
#pragma unroll
                for (int j = 0; j < 4; j++)
                    if (coff + j > roff + i) s[i][j] = -1e30f;
        }

        // ---- online softmax (row reductions over the 16-lane tx group) ----
#pragma unroll
        for (int i = 0; i < 8; i++) {
            float rm = fmaxf(fmaxf(s[i][0], s[i][1]), fmaxf(s[i][2], s[i][3]));
#pragma unroll
            for (int o = 8; o > 0; o >>= 1)
                rm = fmaxf(rm, __shfl_xor_sync(0xffffffffu, rm, o, 16));
            const float mn    = fmaxf(m[i], rm);
            const float alpha = __expf(m[i] - mn);
            float rs = 0.f;
#pragma unroll
            for (int j = 0; j < 4; j++) { s[i][j] = __expf(s[i][j] - mn); rs += s[i][j]; }
#pragma unroll
            for (int o = 8; o > 0; o >>= 1)
                rs += __shfl_xor_sync(0xffffffffu, rs, o, 16);
            l[i] = l[i] * alpha + rs;
            m[i] = mn;
#pragma unroll
            for (int j = 0; j < 8; j++) acc[i][j] *= alpha;
#pragma unroll
            for (int j = 0; j < 4; j++)
                Ps[(ty*8 + i) * PSTRIDE + tx*4 + j] = s[i][j];
        }
        __syncthreads();

        // ---- O += P @ V  (rows ty*8.., cols tx*8..) ----
#pragma unroll 4
        for (int kk = 0; kk < BKT; kk++) {
            float4 v0 = *(const float4*)&Vs[kk * HD + tx*8];
            float4 v1 = *(const float4*)&Vs[kk * HD + tx*8 + 4];
#pragma unroll
            for (int i = 0; i < 8; i++) {
                const float p = Ps[(ty*8 + i) * PSTRIDE + kk];
                acc[i][0] += p*v0.x; acc[i][1] += p*v0.y;
                acc[i][2] += p*v0.z; acc[i][3] += p*v0.w;
                acc[i][4] += p*v1.x; acc[i][5] += p*v1.y;
                acc[i][6] += p*v1.z; acc[i][7] += p*v1.w;
            }
        }
    }

    // ---- epilogue ----
#pragma unroll
    for (int i = 0; i < 8; i++) {
        const float inv = 1.0f / l[i];
        const int row = qb * BQ + ty*8 + i;
        float* Op = O + (size_t)row * DIM + h * HD + tx*8;
        float4 o0, o1;
        o0.x = acc[i][0]*inv; o0.y = acc[i][1]*inv;
        o0.z = acc[i][2]*inv; o0.w = acc[i][3]*inv;
        o1.x = acc[i][4]*inv; o1.y = acc[i][5]*inv;
        o1.z = acc[i][6]*inv; o1.w = acc[i][7]*inv;
        *(float4*)Op       = o0;
        *(float4*)(Op + 4) = o1;
    }
}

// =================================================================
// launch
// =================================================================
#define FLASH_SMEM (((BQ + 2*BKT) * HD + BQ * PSTRIDE) * (int)sizeof(float))

extern "C" void kernel_launch(void* const* d_in, const int* in_sizes, int n_in,
                              void* d_out, int out_size)
{
    const float* x  = (const float*)d_in[0];
    const float* wq = (const float*)d_in[1];
    const float* wk = (const float*)d_in[2];
    const float* wv = (const float*)d_in[3];
    const float* wo = (const float*)d_in[4];
    float* out = (float*)d_out;

    float *Q, *K, *V, *A;
    cudaGetSymbolAddress((void**)&Q, g_Q);
    cudaGetSymbolAddress((void**)&K, g_K);
    cudaGetSymbolAddress((void**)&V, g_V);
    cudaGetSymbolAddress((void**)&A, g_A);

    cudaFuncSetAttribute(gemm_qkv,
                         cudaFuncAttributeMaxDynamicSharedMemorySize, G_SMEM);
    cudaFuncSetAttribute(gemm_nt,
                         cudaFuncAttributeMaxDynamicSharedMemorySize, G_SMEM);
    cudaFuncSetAttribute(flash_kernel,
                         cudaFuncAttributeMaxDynamicSharedMemorySize, FLASH_SMEM);

    // RoPE table (independent of projections)
    rope_table<<<(SEQ * 64 + 255) / 256, 256>>>();

    // fused Q/K/V projections (3xTF32 mma.sync, 8 warps/CTA — R12 shape)
    gemm_qkv<<<dim3(48, SEQ/128), 256, G_SMEM>>>(x, wq, wk, wv);

    // RoPE apply (Q + K fused)
    rope_apply<<<(ROPE_TOTQ + ROPE_TOTK + 255) / 256, 256>>>(Q, K);

    // attention (BQ=128)
    flash_kernel<<<dim3(SEQ/BQ, NH), 256, FLASH_SMEM>>>(Q, K, V, A);

    // output projection
    gemm_nt<<<dim3(DIM/128, SEQ/128), 256, G_SMEM>>>(A, wo, out, DIM, DIM);
}

// round 15
// speedup vs baseline: 1.0754x; 1.0000x over previous
#include <cuda_runtime.h>
#include <math.h>
#include <stdint.h>

#define SEQ   2048
#define DIM   4096
#define NH    32
#define NKV   8
#define HD    128
#define KVDIM (NKV*HD)   /* 1024 */

// ---------------- scratch (no allocations allowed) ----------------
__device__ float  g_Q[SEQ*DIM];
__device__ float  g_K[SEQ*KVDIM];
__device__ float  g_V[SEQ*KVDIM];
__device__ float  g_A[SEQ*DIM];
__device__ float2 g_cs[SEQ*64];     // RoPE cos/sin table

// =================================================================
// portable PTX helpers (family-safe: compiles under compute_103)
// =================================================================
__device__ __forceinline__ uint32_t s2u(const void* p) {
    uint32_t a;
    asm("{ .reg .u64 t; cvta.to.shared.u64 t, %1; cvt.u32.u64 %0, t; }"
        : "=r"(a) : "l"(p));
    return a;
}
__device__ __forceinline__ void cp16(uint32_t dst, const void* src) {
    asm volatile("cp.async.cg.shared.global [%0], [%1], 16;"
                 :: "r"(dst), "l"(src) : "memory");
}
__device__ __forceinline__ void cp_commit() {
    asm volatile("cp.async.commit_group;" ::: "memory");
}
template <int N>
__device__ __forceinline__ void cp_wait() {
    asm volatile("cp.async.wait_group %0;" :: "n"(N) : "memory");
}
// D += A*B  (m16n8k8, tf32 inputs, fp32 accum)
__device__ __forceinline__ void mma_tf32(float* c, const uint32_t* a, const uint32_t* b) {
    asm volatile(
        "mma.sync.aligned.m16n8k8.row.col.f32.tf32.tf32.f32 "
        "{%0,%1,%2,%3}, {%4,%5,%6,%7}, {%8,%9}, {%0,%1,%2,%3};"
        : "+f"(c[0]), "+f"(c[1]), "+f"(c[2]), "+f"(c[3])
        : "r"(a[0]), "r"(a[1]), "r"(a[2]), "r"(a[3]), "r"(b[0]), "r"(b[1]));
}
// v -> (hi, lo): mask-based tf32 split (fast ALU, no F2F cvt).
__device__ __forceinline__ void split_tf32(float v, uint32_t& hi, uint32_t& lo) {
    const uint32_t hb = __float_as_uint(v) & 0xFFFFE000u;
    const float lf = v - __uint_as_float(hb);
    hi = hb;
    lo = __float_as_uint(lf) & 0xFFFFE000u;
}

// =================================================================
// 3xTF32 GEMM core: 128x128 CTA tile, BK=32, 256 threads (8 warps
// 2x4), warp tile 64x32, cp.async double-buffered smem + two-deep
// FRAGMENT pipeline (load ks+1 frags while ks MMAs issue).
// =================================================================
#define GST 36                                  /* smem row stride (floats) */
#define GBUF (128 * GST)                        /* one tile: 4608 floats */
#define G_SMEM (4 * GBUF * (int)sizeof(float))  /* 2 bufs x (A+B) = 73728 B */

__device__ __forceinline__ void gemm_core(
    const float* __restrict__ A, const float* __restrict__ B,
    float* __restrict__ C, int N, int K, int bm, int bn, float* sm)
{
    const uint32_t sb = s2u(sm);
    const int tid = threadIdx.x;
    const int wid = tid >> 5, lane = tid & 31;
    const int g = lane >> 2, tig = lane & 3;
    const int warp_m = wid >> 2, warp_n = wid & 3;

    auto load_chunk = [&](int kc, int buf) {
        const float* Ap = A + (size_t)bm * K + kc * 32;
        const float* Bp = B + (size_t)bn * K + kc * 32;
        const uint32_t ab = sb + (uint32_t)(2 * buf)     * GBUF * 4;
        const uint32_t bb = sb + (uint32_t)(2 * buf + 1) * GBUF * 4;
#pragma unroll
        for (int t = 0; t < 4; t++) {
            int i = tid + t * 256;
            int r = i >> 3, c = (i & 7) * 4;
            uint32_t so = (uint32_t)(r * GST + c) * 4;
            cp16(ab + so, Ap + (size_t)r * K + c);
            cp16(bb + so, Bp + (size_t)r * K + c);
        }
        cp_commit();
    };

    float acc[4][4][4];
#pragma unroll
    for (int i = 0; i < 4; i++)
#pragma unroll
        for (int j = 0; j < 4; j++)
#pragma unroll
            for (int q = 0; q < 4; q++) acc[i][j][q] = 0.f;

    // two-deep fragment pipeline buffers
    uint32_t ah[2][4][4], al[2][4][4], bh[2][4][2], bl[2][4][2];

    auto load_frag = [&](const float* As, const float* Bs, int ks, int pb) {
        const int k0 = ks * 8;
#pragma unroll
        for (int tm = 0; tm < 4; tm++) {
            const int r0 = warp_m * 64 + tm * 16 + g;
            split_tf32(As[ r0      * GST + k0 + tig    ], ah[pb][tm][0], al[pb][tm][0]);
            split_tf32(As[(r0 + 8) * GST + k0 + tig    ], ah[pb][tm][1], al[pb][tm][1]);
            split_tf32(As[ r0      * GST + k0 + tig + 4], ah[pb][tm][2], al[pb][tm][2]);
            split_tf32(As[(r0 + 8) * GST + k0 + tig + 4], ah[pb][tm][3], al[pb][tm][3]);
        }
#pragma unroll
        for (int tn = 0; tn < 4; tn++) {
            const int r0 = warp_n * 32 + tn * 8 + g;
            split_tf32(Bs[r0 * GST + k0 + tig    ], bh[pb][tn][0], bl[pb][tn][0]);
            split_tf32(Bs[r0 * GST + k0 + tig + 4], bh[pb][tn][1], bl[pb][tn][1]);
        }
    };

    const int NC = K >> 5;
    load_chunk(0, 0);

    for (int kc = 0; kc < NC; kc++) {
        if (kc + 1 < NC) { load_chunk(kc + 1, (kc + 1) & 1); cp_wait<1>(); }
        else             { cp_wait<0>(); }
        __syncthreads();

        const float* As = sm + (2 * (kc & 1))     * GBUF;
        const float* Bs = sm + (2 * (kc & 1) + 1) * GBUF;

        load_frag(As, Bs, 0, 0);
#pragma unroll
        for (int ks = 0; ks < 4; ks++) {
            const int pb = ks & 1;
            if (ks < 3) load_frag(As, Bs, ks + 1, pb ^ 1);
            // pass-major order: long dependency distance on each accumulator
#pragma unroll
            for (int tm = 0; tm < 4; tm++)
#pragma unroll
                for (int tn = 0; tn < 4; tn++)
                    mma_tf32(acc[tm][tn], al[pb][tm], bh[pb][tn]);
#pragma unroll
            for (int tm = 0; tm < 4; tm++)
#pragma unroll
                for (int tn = 0; tn < 4; tn++)
                    mma_tf32(acc[tm][tn], ah[pb][tm], bl[pb][tn]);
#pragma unroll
            for (int tm = 0; tm < 4; tm++)
#pragma unroll
                for (int tn = 0; tn < 4; tn++)
                    mma_tf32(acc[tm][tn], ah[pb][tm], bh[pb][tn]);
        }
        __syncthreads();
    }

#pragma unroll
    for (int tm = 0; tm < 4; tm++) {
        const int row = bm + warp_m * 64 + tm * 16 + g;
#pragma unroll
        for (int tn = 0; tn < 4; tn++) {
            const int col = bn + warp_n * 32 + tn * 8 + tig * 2;
            *(float2*)&C[(size_t) row      * N + col] =
                make_float2(acc[tm][tn][0], acc[tm][tn][1]);
            *(float2*)&C[(size_t)(row + 8) * N + col] =
                make_float2(acc[tm][tn][2], acc[tm][tn][3]);
        }
    }
}

// Fused QKV projection: bx 0..31 -> Q, 32..39 -> K, 40..47 -> V
__global__ __launch_bounds__(256, 1)
void gemm_qkv(const float* __restrict__ x, const float* __restrict__ wq,
              const float* __restrict__ wk, const float* __restrict__ wv)
{
    extern __shared__ float sm[];
    const int bx = blockIdx.x;
    const int bm = blockIdx.y * 128;
    const float* B; float* C; int N, bn;
    if (bx < 32)      { B = wq; C = g_Q; N = DIM;   bn = bx * 128; }
    else if (bx < 40) { B = wk; C = g_K; N = KVDIM; bn = (bx - 32) * 128; }
    else              { B = wv; C = g_V; N = KVDIM; bn = (bx - 40) * 128; }
    gemm_core(x, B, C, N, DIM, bm, bn, sm);
}

__global__ __launch_bounds__(256, 1)
void gemm_nt(const float* __restrict__ A, const float* __restrict__ B,
             float* __restrict__ C, int N, int K)
{
    extern __shared__ float sm[];
    gemm_core(A, B, C, N, K, blockIdx.y * 128, blockIdx.x * 128, sm);
}

// =================================================================
// RoPE: table once (double precision) + memory-bound apply (fused Q/K).
// =================================================================
__global__ void rope_table()
{
    int idx = blockIdx.x * blockDim.x + threadIdx.x;
    if (idx >= SEQ * 64) return;
    const int t = idx >> 6, i = idx & 63;
    const double ang = (double)t * pow(500000.0, -(double)i / 64.0);
    g_cs[idx] = make_float2((float)cos(ang), (float)sin(ang));
}

#define ROPE_TOTQ (SEQ * NH  * 64)
#define ROPE_TOTK (SEQ * NKV * 64)

__global__ void rope_apply(float* __restrict__ Xq, float* __restrict__ Xk)
{
    int idx = blockIdx.x * blockDim.x + threadIdx.x;
    float* X; int n_heads;
    if (idx < ROPE_TOTQ) { X = Xq; n_heads = NH; }
    else {
        idx -= ROPE_TOTQ;
        if (idx >= ROPE_TOTK) return;
        X = Xk; n_heads = NKV;
    }
    const int i    = idx & 63;
    const int rest = idx >> 6;
    const int h    = rest % n_heads;
    const int t    = rest / n_heads;

    const float2 cs = g_cs[(t << 6) | i];
    float2* p = (float2*)(X + (((size_t)t * n_heads + h) << 7) + 2 * i);
    const float2 v = *p;
    *p = make_float2(v.x * cs.x - v.y * cs.y, v.x * cs.y + v.y * cs.x);
}

// =================================================================
// Flash attention (causal, GQA 4:1), fp32 SIMT — R14-proven (BQ=128).
// =================================================================
#define BQ  128
#define BKT 64
#define PSTRIDE 68

__device__ __forceinline__ int kswz(int r, int g) {
    return r * HD + ((g ^ ((r >> 2) & 7)) << 2);
}

__global__ __launch_bounds__(256, 1)
void flash_kernel(const float* __restrict__ Q, const float* __restrict__ K,
                  const float* __restrict__ V, float* __restrict__ O)
{
    extern __shared__ float sm[];
    float* Qs = sm;                   // [128][128]
    float* Ks = Qs + BQ  * HD;        // [64][128] swizzled
    float* Vs = Ks + BKT * HD;        // [64][128]
    float* Ps = Vs + BKT * HD;        // [128][68]

    const int qb  = blockIdx.x;
    const int h   = blockIdx.y;
    const int kvh = h >> 2;
    const int tid = threadIdx.x;
    const int tx  = tid & 15;
    const int ty  = tid >> 4;

    const float* Qg = Q + (size_t)qb * BQ * DIM + h * HD;
#pragma unroll
    for (int it = 0; it < 16; it++) {
        int i = tid + it * 256;
        int r = i >> 5, g = i & 31;
        *(float4*)&Qs[r * HD + g * 4] =
            *(const float4*)(Qg + (size_t)r * DIM + g * 4);
    }

    float m[8], l[8], acc[8][8];
#pragma unroll
    for (int i = 0; i < 8; i++) {
        m[i] = -1e30f; l[i] = 0.f;
#pragma unroll
        for (int j = 0; j < 8; j++) acc[i][j] = 0.f;
    }
    const float scale = 0.08838834764831845f;  // 1/sqrt(128)

    const int nkb = 2 * qb + 2;
    for (int kb = 0; kb < nkb; kb++) {
        __syncthreads();

        const float* Kg = K + (size_t)kb * BKT * KVDIM + kvh * HD;
        const float* Vg = V + (size_t)kb * BKT * KVDIM + kvh * HD;
#pragma unroll
        for (int it = 0; it < 8; it++) {
            int i = tid + it * 256;
            int r = i >> 5, g = i & 31;
            *(float4*)&Ks[kswz(r, g)]     = *(const float4*)(Kg + (size_t)r * KVDIM + g * 4);
            *(float4*)&Vs[r * HD + g * 4] = *(const float4*)(Vg + (size_t)r * KVDIM + g * 4);
        }
        __syncthreads();

        float s[8][4];
#pragma unroll
        for (int i = 0; i < 8; i++)
#pragma unroll
            for (int j = 0; j < 4; j++) s[i][j] = 0.f;

#pragma unroll 4
        for (int g = 0; g < 32; g++) {
            float4 kv[4];
#pragma unroll
            for (int j = 0; j < 4; j++)
                kv[j] = *(const float4*)&Ks[kswz(tx*4 + j, g)];
#pragma unroll
            for (int i = 0; i < 8; i++) {
                float4 qv = *(const float4*)&Qs[(ty*8 + i) * HD + g*4];
#pragma unroll
                for (int j = 0; j < 4; j++)
                    s[i][j] += qv.x*kv[j].x + qv.y*kv[j].y
                             + qv.z*kv[j].z + qv.w*kv[j].w;
            }
        }

        const bool diag = (kb >= 2 * qb);
#pragma unroll
        for (int i = 0; i < 8; i++)
#pragma unroll
            for (int j = 0; j < 4; j++) s[i][j] *= scale;
        if (diag) {
            const int roff = qb * BQ + ty * 8;
            const int coff = kb * BKT + tx * 4;
#pragma unroll
            for (int i = 0; i < 8; i++)
#pragma unroll
                for (int j = 0; j < 4; j++)
                    if (coff + j > roff + i) s[i][j] = -1e30f;
        }

#pragma unroll
        for (int i = 0; i < 8; i++) {
            float rm = fmaxf(fmaxf(s[i][0], s[i][1]), fmaxf(s[i][2], s[i][3]));
#pragma unroll
            for (int o = 8; o > 0; o >>= 1)
                rm = fmaxf(rm, __shfl_xor_sync(0xffffffffu, rm, o, 16));
            const float mn    = fmaxf(m[i], rm);
            const float alpha = __expf(m[i] - mn);
            float rs = 0.f;
#pragma unroll
            for (int j = 0; j < 4; j++) { s[i][j] = __expf(s[i][j] - mn); rs += s[i][j]; }
#pragma unroll
            for (int o = 8; o > 0; o >>= 1)
                rs += __shfl_xor_sync(0xffffffffu, rs, o, 16);
            l[i] = l[i] * alpha + rs;
            m[i] = mn;
#pragma unroll
            for (int j = 0; j < 8; j++) acc[i][j] *= alpha;
#pragma unroll
            for (int j = 0; j < 4; j++)
                Ps[(ty*8 + i) * PSTRIDE + tx*4 + j] = s[i][j];
        }
        __syncthreads();

#pragma unroll 4
        for (int kk = 0; kk < BKT; kk++) {
            float4 v0 = *(const float4*)&Vs[kk * HD + tx*8];
            float4 v1 = *(const float4*)&Vs[kk * HD + tx*8 + 4];
#pragma unroll
            for (int i = 0; i < 8; i++) {
                const float p = Ps[(ty*8 + i) * PSTRIDE + kk];
                acc[i][0] += p*v0.x; acc[i][1] += p*v0.y;
                acc[i][2] += p*v0.z; acc[i][3] += p*v0.w;
                acc[i][4] += p*v1.x; acc[i][5] += p*v1.y;
                acc[i][6] += p*v1.z; acc[i][7] += p*v1.w;
            }
        }
    }

#pragma unroll
    for (int i = 0; i < 8; i++) {
        const float inv = 1.0f / l[i];
        const int row = qb * BQ + ty*8 + i;
        float* Op = O + (size_t)row * DIM + h * HD + tx*8;
        float4 o0, o1;
        o0.x = acc[i][0]*inv; o0.y = acc[i][1]*inv;
        o0.z = acc[i][2]*inv; o0.w = acc[i][3]*inv;
        o1.x = acc[i][4]*inv; o1.y = acc[i][5]*inv;
        o1.z = acc[i][6]*inv; o1.w = acc[i][7]*inv;
        *(float4*)Op       = o0;
        *(float4*)(Op + 4) = o1;
    }
}

// =================================================================
// launch
// =================================================================
#define FLASH_SMEM (((BQ + 2*BKT) * HD + BQ * PSTRIDE) * (int)sizeof(float))

extern "C" void kernel_launch(void* const* d_in, const int* in_sizes, int n_in,
                              void* d_out, int out_size)
{
    const float* x  = (const float*)d_in[0];
    const float* wq = (const float*)d_in[1];
    const float* wk = (const float*)d_in[2];
    const float* wv = (const float*)d_in[3];
    const float* wo = (const float*)d_in[4];
    float* out = (float*)d_out;

    float *Q, *K, *V, *A;
    cudaGetSymbolAddress((void**)&Q, g_Q);
    cudaGetSymbolAddress((void**)&K, g_K);
    cudaGetSymbolAddress((void**)&V, g_V);
    cudaGetSymbolAddress((void**)&A, g_A);

    cudaFuncSetAttribute(gemm_qkv,
                         cudaFuncAttributeMaxDynamicSharedMemorySize, G_SMEM);
    cudaFuncSetAttribute(gemm_nt,
                         cudaFuncAttributeMaxDynamicSharedMemorySize, G_SMEM);
    cudaFuncSetAttribute(flash_kernel,
                         cudaFuncAttributeMaxDynamicSharedMemorySize, FLASH_SMEM);

    // RoPE table (independent of projections)
    rope_table<<<(SEQ * 64 + 255) / 256, 256>>>();

    // fused Q/K/V projections (3xTF32 mma.sync + fragment pipeline)
    gemm_qkv<<<dim3(48, SEQ/128), 256, G_SMEM>>>(x, wq, wk, wv);

    // RoPE apply (Q + K fused)
    rope_apply<<<(ROPE_TOTQ + ROPE_TOTK + 255) / 256, 256>>>(Q, K);

    // attention (BQ=128)
    flash_kernel<<<dim3(SEQ/BQ, NH), 256, FLASH_SMEM>>>(Q, K, V, A);

    // output projection
    gemm_nt<<<dim3(DIM/128, SEQ/128), 256, G_SMEM>>>(A, wo, out, DIM, DIM);
}

// round 16
// speedup vs baseline: 1.2991x; 1.2080x over previous
#include <cuda_runtime.h>
#include <math.h>
#include <stdint.h>

#define SEQ   2048
#define DIM   4096
#define NH    32
#define NKV   8
#define HD    128
#define KVDIM (NKV*HD)   /* 1024 */

// ---------------- scratch (no allocations allowed) ----------------
__device__ float  g_Q[SEQ*DIM];
__device__ float  g_K[SEQ*KVDIM];
__device__ float  g_V[SEQ*KVDIM];
__device__ float  g_A[SEQ*DIM];
__device__ float2 g_cs[SEQ*64];     // RoPE cos/sin table

// =================================================================
// portable PTX helpers (family-safe: compiles under compute_103)
// =================================================================
__device__ __forceinline__ uint32_t s2u(const void* p) {
    uint32_t a;
    asm("{ .reg .u64 t; cvta.to.shared.u64 t, %1; cvt.u32.u64 %0, t; }"
        : "=r"(a) : "l"(p));
    return a;
}
__device__ __forceinline__ void cp16(uint32_t dst, const void* src) {
    asm volatile("cp.async.cg.shared.global [%0], [%1], 16;"
                 :: "r"(dst), "l"(src) : "memory");
}
__device__ __forceinline__ void cp_commit() {
    asm volatile("cp.async.commit_group;" ::: "memory");
}
template <int N>
__device__ __forceinline__ void cp_wait() {
    asm volatile("cp.async.wait_group %0;" :: "n"(N) : "memory");
}
// D += A*B  (m16n8k16, bf16 inputs, fp32 accum)
__device__ __forceinline__ void mma_bf16(float* c, const uint32_t* a, const uint32_t* b) {
    asm volatile(
        "mma.sync.aligned.m16n8k16.row.col.f32.bf16.bf16.f32 "
        "{%0,%1,%2,%3}, {%4,%5,%6,%7}, {%8,%9}, {%0,%1,%2,%3};"
        : "+f"(c[0]), "+f"(c[1]), "+f"(c[2]), "+f"(c[3])
        : "r"(a[0]), "r"(a[1]), "r"(a[2]), "r"(a[3]), "r"(b[0]), "r"(b[1]));
}
// float2 -> (hi bf16x2, lo bf16x2), elem .x in LOW half, .y in HIGH.
// RN conversion; lo = v - float(hi) is Sterbenz-exact; residual ~2^-18|v|.
__device__ __forceinline__ void split_bf16(float2 v, uint32_t& hp, uint32_t& lp) {
    uint32_t h;
    asm("cvt.rn.bf16x2.f32 %0, %1, %2;" : "=r"(h) : "f"(v.y), "f"(v.x));
    const float h0 = __uint_as_float(h << 16);
    const float h1 = __uint_as_float(h & 0xFFFF0000u);
    const float l0 = v.x - h0;
    const float l1 = v.y - h1;
    uint32_t l;
    asm("cvt.rn.bf16x2.f32 %0, %1, %2;" : "=r"(l) : "f"(l1), "f"(l0));
    hp = h; lp = l;
}

// =================================================================
// 3xBF16 GEMM core: C[.,N] = A[.,K] * B[N,K]^T (row-major, K contig)
// 128x128 CTA tile, BK=32 (2 x k16 steps), 256 threads (8 warps 2x4),
// warp tile 64x32. cp.async double-buffered raw fp32 smem; RN bf16
// 2-term split at fragment load; passes: al*bh, ah*bl, ah*bh.
// =================================================================
#define GST 36                                  /* smem row stride (floats) */
#define GBUF (128 * GST)                        /* one tile: 4608 floats */
#define G_SMEM (4 * GBUF * (int)sizeof(float))  /* 2 bufs x (A+B) = 73728 B */

__device__ __forceinline__ void gemm_core(
    const float* __restrict__ A, const float* __restrict__ B,
    float* __restrict__ C, int N, int K, int bm, int bn, float* sm)
{
    const uint32_t sb = s2u(sm);
    const int tid = threadIdx.x;
    const int wid = tid >> 5, lane = tid & 31;
    const int g = lane >> 2, tig = lane & 3;
    const int warp_m = wid >> 2, warp_n = wid & 3;

    auto load_chunk = [&](int kc, int buf) {
        const float* Ap = A + (size_t)bm * K + kc * 32;
        const float* Bp = B + (size_t)bn * K + kc * 32;
        const uint32_t ab = sb + (uint32_t)(2 * buf)     * GBUF * 4;
        const uint32_t bb = sb + (uint32_t)(2 * buf + 1) * GBUF * 4;
#pragma unroll
        for (int t = 0; t < 4; t++) {
            int i = tid + t * 256;
            int r = i >> 3, c = (i & 7) * 4;
            uint32_t so = (uint32_t)(r * GST + c) * 4;
            cp16(ab + so, Ap + (size_t)r * K + c);
            cp16(bb + so, Bp + (size_t)r * K + c);
        }
        cp_commit();
    };

    float acc[4][4][4];
#pragma unroll
    for (int i = 0; i < 4; i++)
#pragma unroll
        for (int j = 0; j < 4; j++)
#pragma unroll
            for (int q = 0; q < 4; q++) acc[i][j][q] = 0.f;

    const int NC = K >> 5;
    load_chunk(0, 0);

    for (int kc = 0; kc < NC; kc++) {
        if (kc + 1 < NC) { load_chunk(kc + 1, (kc + 1) & 1); cp_wait<1>(); }
        else             { cp_wait<0>(); }
        __syncthreads();

        const float* As = sm + (2 * (kc & 1))     * GBUF;
        const float* Bs = sm + (2 * (kc & 1) + 1) * GBUF;

#pragma unroll
        for (int ks = 0; ks < 2; ks++) {              // 2 x k16 per 32-chunk
            const int k0 = ks * 16;
            uint32_t ah[4][4], al[4][4], bh[4][2], bl[4][2];
#pragma unroll
            for (int tm = 0; tm < 4; tm++) {
                const int r0 = warp_m * 64 + tm * 16 + g;
                // a0=A[g][2t,2t+1] a1=A[g+8][..] a2=A[g][2t+8,+9] a3=A[g+8][..]
                float2 v00 = *(const float2*)&As[ r0      * GST + k0 + tig*2    ];
                float2 v10 = *(const float2*)&As[(r0 + 8) * GST + k0 + tig*2    ];
                float2 v01 = *(const float2*)&As[ r0      * GST + k0 + tig*2 + 8];
                float2 v11 = *(const float2*)&As[(r0 + 8) * GST + k0 + tig*2 + 8];
                split_bf16(v00, ah[tm][0], al[tm][0]);
                split_bf16(v10, ah[tm][1], al[tm][1]);
                split_bf16(v01, ah[tm][2], al[tm][2]);
                split_bf16(v11, ah[tm][3], al[tm][3]);
            }
#pragma unroll
            for (int tn = 0; tn < 4; tn++) {
                const int r0 = warp_n * 32 + tn * 8 + g;
                // b0=B[2t,2t+1][g] b1=B[2t+8,+9][g]  (k x n, col-major)
                float2 w0 = *(const float2*)&Bs[r0 * GST + k0 + tig*2    ];
                float2 w1 = *(const float2*)&Bs[r0 * GST + k0 + tig*2 + 8];
                split_bf16(w0, bh[tn][0], bl[tn][0]);
                split_bf16(w1, bh[tn][1], bl[tn][1]);
            }
            // pass-major order: long dependency distance on each accumulator
#pragma unroll
            for (int tm = 0; tm < 4; tm++)
#pragma unroll
                for (int tn = 0; tn < 4; tn++)
                    mma_bf16(acc[tm][tn], al[tm], bh[tn]);
#pragma unroll
            for (int tm = 0; tm < 4; tm++)
#pragma unroll
                for (int tn = 0; tn < 4; tn++)
                    mma_bf16(acc[tm][tn], ah[tm], bl[tn]);
#pragma unroll
            for (int tm = 0; tm < 4; tm++)
#pragma unroll
                for (int tn = 0; tn < 4; tn++)
                    mma_bf16(acc[tm][tn], ah[tm], bh[tn]);
        }
        __syncthreads();
    }

#pragma unroll
    for (int tm = 0; tm < 4; tm++) {
        const int row = bm + warp_m * 64 + tm * 16 + g;
#pragma unroll
        for (int tn = 0; tn < 4; tn++) {
            const int col = bn + warp_n * 32 + tn * 8 + tig * 2;
            *(float2*)&C[(size_t) row      * N + col] =
                make_float2(acc[tm][tn][0], acc[tm][tn][1]);
            *(float2*)&C[(size_t)(row + 8) * N + col] =
                make_float2(acc[tm][tn][2], acc[tm][tn][3]);
        }
    }
}

// Fused QKV projection: bx 0..31 -> Q, 32..39 -> K, 40..47 -> V
__global__ __launch_bounds__(256, 1)
void gemm_qkv(const float* __restrict__ x, const float* __restrict__ wq,
              const float* __restrict__ wk, const float* __restrict__ wv)
{
    extern __shared__ float sm[];
    const int bx = blockIdx.x;
    const int bm = blockIdx.y * 128;
    const float* B; float* C; int N, bn;
    if (bx < 32)      { B = wq; C = g_Q; N = DIM;   bn = bx * 128; }
    else if (bx < 40) { B = wk; C = g_K; N = KVDIM; bn = (bx - 32) * 128; }
    else              { B = wv; C = g_V; N = KVDIM; bn = (bx - 40) * 128; }
    gemm_core(x, B, C, N, DIM, bm, bn, sm);
}

__global__ __launch_bounds__(256, 1)
void gemm_nt(const float* __restrict__ A, const float* __restrict__ B,
             float* __restrict__ C, int N, int K)
{
    extern __shared__ float sm[];
    gemm_core(A, B, C, N, K, blockIdx.y * 128, blockIdx.x * 128, sm);
}

// =================================================================
// RoPE: table once (double precision) + memory-bound apply (fused Q/K).
// =================================================================
__global__ void rope_table()
{
    int idx = blockIdx.x * blockDim.x + threadIdx.x;
    if (idx >= SEQ * 64) return;
    const int t = idx >> 6, i = idx & 63;
    const double ang = (double)t * pow(500000.0, -(double)i / 64.0);
    g_cs[idx] = make_float2((float)cos(ang), (float)sin(ang));
}

#define ROPE_TOTQ (SEQ * NH  * 64)
#define ROPE_TOTK (SEQ * NKV * 64)

__global__ void rope_apply(float* __restrict__ Xq, float* __restrict__ Xk)
{
    int idx = blockIdx.x * blockDim.x + threadIdx.x;
    float* X; int n_heads;
    if (idx < ROPE_TOTQ) { X = Xq; n_heads = NH; }
    else {
        idx -= ROPE_TOTQ;
        if (idx >= ROPE_TOTK) return;
        X = Xk; n_heads = NKV;
    }
    const int i    = idx & 63;
    const int rest = idx >> 6;
    const int h    = rest % n_heads;
    const int t    = rest / n_heads;

    const float2 cs = g_cs[(t << 6) | i];
    float2* p = (float2*)(X + (((size_t)t * n_heads + h) << 7) + 2 * i);
    const float2 v = *p;
    *p = make_float2(v.x * cs.x - v.y * cs.y, v.x * cs.y + v.y * cs.x);
}

// =================================================================
// Flash attention (causal, GQA 4:1), fp32 SIMT — R14-proven (BQ=128).
// =================================================================
#define BQ  128
#define BKT 64
#define PSTRIDE 68

__device__ __forceinline__ int kswz(int r, int g) {
    return r * HD + ((g ^ ((r >> 2) & 7)) << 2);
}

__global__ __launch_bounds__(256, 1)
void flash_kernel(const float* __restrict__ Q, const float* __restrict__ K,
                  const float* __restrict__ V, float* __restrict__ O)
{
    extern __shared__ float sm[];
    float* Qs = sm;                   // [128][128]
    float* Ks = Qs + BQ  * HD;        // [64][128] swizzled
    float* Vs = Ks + BKT * HD;        // [64][128]
    float* Ps = Vs + BKT * HD;        // [128][68]

    const int qb  = blockIdx.x;
    const int h   = blockIdx.y;
    const int kvh = h >> 2;
    const int tid = threadIdx.x;
    const int tx  = tid & 15;
    const int ty  = tid >> 4;

    const float* Qg = Q + (size_t)qb * BQ * DIM + h * HD;
#pragma unroll
    for (int it = 0; it < 16; it++) {
        int i = tid + it * 256;
        int r = i >> 5, g = i & 31;
        *(float4*)&Qs[r * HD + g * 4] =
            *(const float4*)(Qg + (size_t)r * DIM + g * 4);
    }

    float m[8], l[8], acc[8][8];
#pragma unroll
    for (int i = 0; i < 8; i++) {
        m[i] = -1e30f; l[i] = 0.f;
#pragma unroll
        for (int j = 0; j < 8; j++) acc[i][j] = 0.f;
    }
    const float scale = 0.08838834764831845f;  // 1/sqrt(128)

    const int nkb = 2 * qb + 2;
    for (int kb = 0; kb < nkb; kb++) {
        __syncthreads();

        const float* Kg = K + (size_t)kb * BKT * KVDIM + kvh * HD;
        const float* Vg = V + (size_t)kb * BKT * KVDIM + kvh * HD;
#pragma unroll
        for (int it = 0; it < 8; it++) {
            int i = tid + it * 256;
            int r = i >> 5, g = i & 31;
            *(float4*)&Ks[kswz(r, g)]     = *(const float4*)(Kg + (size_t)r * KVDIM + g * 4);
            *(float4*)&Vs[r * HD + g * 4] = *(const float4*)(Vg + (size_t)r * KVDIM + g * 4);
        }
        __syncthreads();

        float s[8][4];
#pragma unroll
        for (int i = 0; i < 8; i++)
#pragma unroll
            for (int j = 0; j < 4; j++) s[i][j] = 0.f;

#pragma unroll 4
        for (int g = 0; g < 32; g++) {
            float4 kv[4];
#pragma unroll
            for (int j = 0; j < 4; j++)
                kv[j] = *(const float4*)&Ks[kswz(tx*4 + j, g)];
#pragma unroll
            for (int i = 0; i < 8; i++) {
                float4 qv = *(const float4*)&Qs[(ty*8 + i) * HD + g*4];
#pragma unroll
                for (int j = 0; j < 4; j++)
                    s[i][j] += qv.x*kv[j].x + qv.y*kv[j].y
                             + qv.z*kv[j].z + qv.w*kv[j].w;
            }
        }

        const bool diag = (kb >= 2 * qb);
#pragma unroll
        for (int i = 0; i < 8; i++)
#pragma unroll
            for (int j = 0; j < 4; j++) s[i][j] *= scale;
        if (diag) {
            const int roff = qb * BQ + ty * 8;
            const int coff = kb * BKT + tx * 4;
#pragma unroll
            for (int i = 0; i < 8; i++)
#pragma unroll
                for (int j = 0; j < 4; j++)
                    if (coff + j > roff + i) s[i][j] = -1e30f;
        }

#pragma unroll
        for (int i = 0; i < 8; i++) {
            float rm = fmaxf(fmaxf(s[i][0], s[i][1]), fmaxf(s[i][2], s[i][3]));
#pragma unroll
            for (int o = 8; o > 0; o >>= 1)
                rm = fmaxf(rm, __shfl_xor_sync(0xffffffffu, rm, o, 16));
            const float mn    = fmaxf(m[i], rm);
            const float alpha = __expf(m[i] - mn);
            float rs = 0.f;
#pragma unroll
            for (int j = 0; j < 4; j++) { s[i][j] = __expf(s[i][j] - mn); rs += s[i][j]; }
#pragma unroll
            for (int o = 8; o > 0; o >>= 1)
                rs += __shfl_xor_sync(0xffffffffu, rs, o, 16);
            l[i] = l[i] * alpha + rs;
            m[i] = mn;
#pragma unroll
            for (int j = 0; j < 8; j++) acc[i][j] *= alpha;
#pragma unroll
            for (int j = 0; j < 4; j++)
                Ps[(ty*8 + i) * PSTRIDE + tx*4 + j] = s[i][j];
        }
        __syncthreads();

#pragma unroll 4
        for (int kk = 0; kk < BKT; kk++) {
            float4 v0 = *(const float4*)&Vs[kk * HD + tx*8];
            float4 v1 = *(const float4*)&Vs[kk * HD + tx*8 + 4];
#pragma unroll
            for (int i = 0; i < 8; i++) {
                const float p = Ps[(ty*8 + i) * PSTRIDE + kk];
                acc[i][0] += p*v0.x; acc[i][1] += p*v0.y;
                acc[i][2] += p*v0.z; acc[i][3] += p*v0.w;
                acc[i][4] += p*v1.x; acc[i][5] += p*v1.y;
                acc[i][6] += p*v1.z; acc[i][7] += p*v1.w;
            }
        }
    }

#pragma unroll
    for (int i = 0; i < 8; i++) {
        const float inv = 1.0f / l[i];
        const int row = qb * BQ + ty*8 + i;
        float* Op = O + (size_t)row * DIM + h * HD + tx*8;
        float4 o0, o1;
        o0.x = acc[i][0]*inv; o0.y = acc[i][1]*inv;
        o0.z = acc[i][2]*inv; o0.w = acc[i][3]*inv;
        o1.x = acc[i][4]*inv; o1.y = acc[i][5]*inv;
        o1.z = acc[i][6]*inv; o1.w = acc[i][7]*inv;
        *(float4*)Op       = o0;
        *(float4*)(Op + 4) = o1;
    }
}

// =================================================================
// launch
// =================================================================
#define FLASH_SMEM (((BQ + 2*BKT) * HD + BQ * PSTRIDE) * (int)sizeof(float))

extern "C" void kernel_launch(void* const* d_in, const int* in_sizes, int n_in,
                              void* d_out, int out_size)
{
    const float* x  = (const float*)d_in[0];
    const float* wq = (const float*)d_in[1];
    const float* wk = (const float*)d_in[2];
    const float* wv = (const float*)d_in[3];
    const float* wo = (const float*)d_in[4];
    float* out = (float*)d_out;

    float *Q, *K, *V, *A;
    cudaGetSymbolAddress((void**)&Q, g_Q);
    cudaGetSymbolAddress((void**)&K, g_K);
    cudaGetSymbolAddress((void**)&V, g_V);
    cudaGetSymbolAddress((void**)&A, g_A);

    cudaFuncSetAttribute(gemm_qkv,
                         cudaFuncAttributeMaxDynamicSharedMemorySize, G_SMEM);
    cudaFuncSetAttribute(gemm_nt,
                         cudaFuncAttributeMaxDynamicSharedMemorySize, G_SMEM);
    cudaFuncSetAttribute(flash_kernel,
                         cudaFuncAttributeMaxDynamicSharedMemorySize, FLASH_SMEM);

    // RoPE table (independent of projections)
    rope_table<<<(SEQ * 64 + 255) / 256, 256>>>();

    // fused Q/K/V projections (3xBF16 m16n8k16 mma.sync)
    gemm_qkv<<<dim3(48, SEQ/128), 256, G_SMEM>>>(x, wq, wk, wv);

    // RoPE apply (Q + K fused)
    rope_apply<<<(ROPE_TOTQ + ROPE_TOTK + 255) / 256, 256>>>(Q, K);

    // attention (BQ=128)
    flash_kernel<<<dim3(SEQ/BQ, NH), 256, FLASH_SMEM>>>(Q, K, V, A);

    // output projection (3xBF16)
    gemm_nt<<<dim3(DIM/128, SEQ/128), 256, G_SMEM>>>(A, wo, out, DIM, DIM);
}

// round 17
// speedup vs baseline: 1.3692x; 1.0540x over previous
#include <cuda_runtime.h>
#include <math.h>
#include <stdint.h>

#define SEQ   2048
#define DIM   4096
#define NH    32
#define NKV   8
#define HD    128
#define KVDIM (NKV*HD)   /* 1024 */

// ---------------- scratch (no allocations allowed) ----------------
__device__ float  g_Q[SEQ*DIM];
__device__ float  g_K[SEQ*KVDIM];
__device__ float  g_V[SEQ*KVDIM];
__device__ float2 g_cs[SEQ*64];     // RoPE cos/sin table

// packed bf16-pair planes (elem 2i in low half, 2i+1 in high half)
__device__ uint32_t g_xh [SEQ*DIM/2],   g_xl [SEQ*DIM/2];
__device__ uint32_t g_wqh[DIM*DIM/2],   g_wql[DIM*DIM/2];
__device__ uint32_t g_wkh[KVDIM*DIM/2], g_wkl[KVDIM*DIM/2];
__device__ uint32_t g_wvh[KVDIM*DIM/2], g_wvl[KVDIM*DIM/2];
__device__ uint32_t g_woh[DIM*DIM/2],   g_wol[DIM*DIM/2];
__device__ uint32_t g_Ah [SEQ*DIM/2],   g_Al [SEQ*DIM/2];

// =================================================================
// portable PTX helpers
// =================================================================
__device__ __forceinline__ uint32_t s2u(const void* p) {
    uint32_t a;
    asm("{ .reg .u64 t; cvta.to.shared.u64 t, %1; cvt.u32.u64 %0, t; }"
        : "=r"(a) : "l"(p));
    return a;
}
__device__ __forceinline__ void cp16(uint32_t dst, const void* src) {
    asm volatile("cp.async.cg.shared.global [%0], [%1], 16;"
                 :: "r"(dst), "l"(src) : "memory");
}
__device__ __forceinline__ void cp_commit() {
    asm volatile("cp.async.commit_group;" ::: "memory");
}
template <int N>
__device__ __forceinline__ void cp_wait() {
    asm volatile("cp.async.wait_group %0;" :: "n"(N) : "memory");
}
// D += A*B  (m16n8k16, bf16 inputs, fp32 accum)
__device__ __forceinline__ void mma_bf16(float* c, const uint32_t* a, const uint32_t* b) {
    asm volatile(
        "mma.sync.aligned.m16n8k16.row.col.f32.bf16.bf16.f32 "
        "{%0,%1,%2,%3}, {%4,%5,%6,%7}, {%8,%9}, {%0,%1,%2,%3};"
        : "+f"(c[0]), "+f"(c[1]), "+f"(c[2]), "+f"(c[3])
        : "r"(a[0]), "r"(a[1]), "r"(a[2]), "r"(a[3]), "r"(b[0]), "r"(b[1]));
}
// float2 -> (hi bf16x2, lo bf16x2); RN; lo = v - float(hi) Sterbenz-exact.
__device__ __forceinline__ void split_bf16(float2 v, uint32_t& hp, uint32_t& lp) {
    uint32_t h;
    asm("cvt.rn.bf16x2.f32 %0, %1, %2;" : "=r"(h) : "f"(v.y), "f"(v.x));
    const float h0 = __uint_as_float(h << 16);
    const float h1 = __uint_as_float(h & 0xFFFF0000u);
    const float l0 = v.x - h0;
    const float l1 = v.y - h1;
    uint32_t l;
    asm("cvt.rn.bf16x2.f32 %0, %1, %2;" : "=r"(l) : "f"(l1), "f"(l0));
    hp = h; lp = l;
}

// split a fp32 tensor into packed bf16-pair planes (one-time, mem-bound)
__global__ void split_plane(const float2* __restrict__ src,
                            uint32_t* __restrict__ hi, uint32_t* __restrict__ lo,
                            int n2)
{
    int i = blockIdx.x * blockDim.x + threadIdx.x;
    if (i >= n2) return;
    uint32_t h, l;
    split_bf16(src[i], h, l);
    hi[i] = h; lo[i] = l;
}

// =================================================================
// 3xBF16 GEMM core on pre-split planes.
// C[.,N] = A[.,K] * B[N,K]^T. 128x128 CTA tile, BK=32 (2 k16 steps),
// 256 threads (8 warps 2x4), warp tile 64x32. Fragment loads are bare
// LDS.32 from bf16 planes (zero ALU in the mainloop).
// =================================================================
#define SMB 40                                   /* uint16 per 32-elem row */
#define PSZ (128 * SMB * 2)                      /* one plane: 10240 B */
#define G_SMEM (8 * PSZ)                         /* 2 bufs x 4 planes = 81920 B */

__device__ __forceinline__ void gemm_core(
    const uint32_t* __restrict__ Ah, const uint32_t* __restrict__ Al,
    const uint32_t* __restrict__ Bh, const uint32_t* __restrict__ Bl,
    float* __restrict__ C, int N, int K, int bm, int bn, char* sm)
{
    const uint32_t sb = s2u(sm);
    const int tid = threadIdx.x;
    const int wid = tid >> 5, lane = tid & 31;
    const int g = lane >> 2, tig = lane & 3;
    const int warp_m = wid >> 2, warp_n = wid & 3;

    auto load_chunk = [&](int kc, int buf) {
        const uint32_t b0 = sb + (uint32_t)buf * 4 * PSZ;
        const size_t koff = (size_t)kc * 32;
#pragma unroll
        for (int p = 0; p < 4; p++) {
            const uint32_t* src = (p == 0) ? Ah : (p == 1) ? Al : (p == 2) ? Bh : Bl;
            const int row0 = (p < 2) ? bm : bn;
            const uint32_t db = b0 + (uint32_t)p * PSZ;
#pragma unroll
            for (int t = 0; t < 2; t++) {
                int i = tid + t * 256;          // 0..511
                int r = i >> 2, c = (i & 3) * 8;
                cp16(db + (uint32_t)(r * SMB + c) * 2,
                     (const char*)src + ((size_t)(row0 + r) * K + koff + c) * 2);
            }
        }
        cp_commit();
    };

    float acc[4][4][4];
#pragma unroll
    for (int i = 0; i < 4; i++)
#pragma unroll
        for (int j = 0; j < 4; j++)
#pragma unroll
            for (int q = 0; q < 4; q++) acc[i][j][q] = 0.f;

    const int NC = K >> 5;
    load_chunk(0, 0);

    for (int kc = 0; kc < NC; kc++) {
        if (kc + 1 < NC) { load_chunk(kc + 1, (kc + 1) & 1); cp_wait<1>(); }
        else             { cp_wait<0>(); }
        __syncthreads();

        const char* bufp = sm + (size_t)(kc & 1) * 4 * PSZ;
        const uint16_t* Ahs = (const uint16_t*)(bufp);
        const uint16_t* Als = (const uint16_t*)(bufp + PSZ);
        const uint16_t* Bhs = (const uint16_t*)(bufp + 2 * PSZ);
        const uint16_t* Bls = (const uint16_t*)(bufp + 3 * PSZ);

#pragma unroll
        for (int ks = 0; ks < 2; ks++) {
            const int kb_ = ks * 16 + tig * 2;
            uint32_t ah[4][4], al[4][4], bh[4][2], bl[4][2];
#pragma unroll
            for (int tm = 0; tm < 4; tm++) {
                const int r0 = warp_m * 64 + tm * 16 + g;
                ah[tm][0] = *(const uint32_t*)&Ahs[ r0      * SMB + kb_    ];
                ah[tm][1] = *(const uint32_t*)&Ahs[(r0 + 8) * SMB + kb_    ];
                ah[tm][2] = *(const uint32_t*)&Ahs[ r0      * SMB + kb_ + 8];
                ah[tm][3] = *(const uint32_t*)&Ahs[(r0 + 8) * SMB + kb_ + 8];
                al[tm][0] = *(const uint32_t*)&Als[ r0      * SMB + kb_    ];
                al[tm][1] = *(const uint32_t*)&Als[(r0 + 8) * SMB + kb_    ];
                al[tm][2] = *(const uint32_t*)&Als[ r0      * SMB + kb_ + 8];
                al[tm][3] = *(const uint32_t*)&Als[(r0 + 8) * SMB + kb_ + 8];
            }
#pragma unroll
            for (int tn = 0; tn < 4; tn++) {
                const int r0 = warp_n * 32 + tn * 8 + g;
                bh[tn][0] = *(const uint32_t*)&Bhs[r0 * SMB + kb_    ];
                bh[tn][1] = *(const uint32_t*)&Bhs[r0 * SMB + kb_ + 8];
                bl[tn][0] = *(const uint32_t*)&Bls[r0 * SMB + kb_    ];
                bl[tn][1] = *(const uint32_t*)&Bls[r0 * SMB + kb_ + 8];
            }
            // pass-major order: long dependency distance on each accumulator
#pragma unroll
            for (int tm = 0; tm < 4; tm++)
#pragma unroll
                for (int tn = 0; tn < 4; tn++)
                    mma_bf16(acc[tm][tn], al[tm], bh[tn]);
#pragma unroll
            for (int tm = 0; tm < 4; tm++)
#pragma unroll
                for (int tn = 0; tn < 4; tn++)
                    mma_bf16(acc[tm][tn], ah[tm], bl[tn]);
#pragma unroll
            for (int tm = 0; tm < 4; tm++)
#pragma unroll
                for (int tn = 0; tn < 4; tn++)
                    mma_bf16(acc[tm][tn], ah[tm], bh[tn]);
        }
        __syncthreads();
    }

#pragma unroll
    for (int tm = 0; tm < 4; tm++) {
        const int row = bm + warp_m * 64 + tm * 16 + g;
#pragma unroll
        for (int tn = 0; tn < 4; tn++) {
            const int col = bn + warp_n * 32 + tn * 8 + tig * 2;
            *(float2*)&C[(size_t) row      * N + col] =
                make_float2(acc[tm][tn][0], acc[tm][tn][1]);
            *(float2*)&C[(size_t)(row + 8) * N + col] =
                make_float2(acc[tm][tn][2], acc[tm][tn][3]);
        }
    }
}

// Fused QKV projection: bx 0..31 -> Q, 32..39 -> K, 40..47 -> V
__global__ __launch_bounds__(256, 1)
void gemm_qkv()
{
    extern __shared__ char smc[];
    const int bx = blockIdx.x;
    const int bm = blockIdx.y * 128;
    const uint32_t *Bh, *Bl; float* C; int N, bn;
    if (bx < 32)      { Bh = g_wqh; Bl = g_wql; C = g_Q; N = DIM;   bn = bx * 128; }
    else if (bx < 40) { Bh = g_wkh; Bl = g_wkl; C = g_K; N = KVDIM; bn = (bx - 32) * 128; }
    else              { Bh = g_wvh; Bl = g_wvl; C = g_V; N = KVDIM; bn = (bx - 40) * 128; }
    gemm_core(g_xh, g_xl, Bh, Bl, C, N, DIM, bm, bn, smc);
}

// output projection: out = A @ wo^T from pre-split planes
__global__ __launch_bounds__(256, 1)
void gemm_out(float* __restrict__ out)
{
    extern __shared__ char smc[];
    gemm_core(g_Ah, g_Al, g_woh, g_wol, out, DIM, DIM,
              blockIdx.y * 128, blockIdx.x * 128, smc);
}

// =================================================================
// RoPE: table once (double precision) + memory-bound apply (fused Q/K).
// =================================================================
__global__ void rope_table()
{
    int idx = blockIdx.x * blockDim.x + threadIdx.x;
    if (idx >= SEQ * 64) return;
    const int t = idx >> 6, i = idx & 63;
    const double ang = (double)t * pow(500000.0, -(double)i / 64.0);
    g_cs[idx] = make_float2((float)cos(ang), (float)sin(ang));
}

#define ROPE_TOTQ (SEQ * NH  * 64)
#define ROPE_TOTK (SEQ * NKV * 64)

__global__ void rope_apply(float* __restrict__ Xq, float* __restrict__ Xk)
{
    int idx = blockIdx.x * blockDim.x + threadIdx.x;
    float* X; int n_heads;
    if (idx < ROPE_TOTQ) { X = Xq; n_heads = NH; }
    else {
        idx -= ROPE_TOTQ;
        if (idx >= ROPE_TOTK) return;
        X = Xk; n_heads = NKV;
    }
    const int i    = idx & 63;
    const int rest = idx >> 6;
    const int h    = rest % n_heads;
    const int t    = rest / n_heads;

    const float2 cs = g_cs[(t << 6) | i];
    float2* p = (float2*)(X + (((size_t)t * n_heads + h) << 7) + 2 * i);
    const float2 v = *p;
    *p = make_float2(v.x * cs.x - v.y * cs.y, v.x * cs.y + v.y * cs.x);
}

// =================================================================
// Flash attention (causal, GQA 4:1), fp32 SIMT — R14-proven (BQ=128).
// Epilogue writes O as pre-split bf16 planes for the out-projection.
// =================================================================
#define BQ  128
#define BKT 64
#define PSTRIDE 68

__device__ __forceinline__ int kswz(int r, int g) {
    return r * HD + ((g ^ ((r >> 2) & 7)) << 2);
}

__global__ __launch_bounds__(256, 1)
void flash_kernel(const float* __restrict__ Q, const float* __restrict__ K,
                  const float* __restrict__ V)
{
    extern __shared__ float sm[];
    float* Qs = sm;                   // [128][128]
    float* Ks = Qs + BQ  * HD;        // [64][128] swizzled
    float* Vs = Ks + BKT * HD;        // [64][128]
    float* Ps = Vs + BKT * HD;        // [128][68]

    const int qb  = blockIdx.x;
    const int h   = blockIdx.y;
    const int kvh = h >> 2;
    const int tid = threadIdx.x;
    const int tx  = tid & 15;
    const int ty  = tid >> 4;

    const float* Qg = Q + (size_t)qb * BQ * DIM + h * HD;
#pragma unroll
    for (int it = 0; it < 16; it++) {
        int i = tid + it * 256;
        int r = i >> 5, g = i & 31;
        *(float4*)&Qs[r * HD + g * 4] =
            *(const float4*)(Qg + (size_t)r * DIM + g * 4);
    }

    float m[8], l[8], acc[8][8];
#pragma unroll
    for (int i = 0; i < 8; i++) {
        m[i] = -1e30f; l[i] = 0.f;
#pragma unroll
        for (int j = 0; j < 8; j++) acc[i][j] = 0.f;
    }
    const float scale = 0.08838834764831845f;  // 1/sqrt(128)

    const int nkb = 2 * qb + 2;
    for (int kb = 0; kb < nkb; kb++) {
        __syncthreads();

        const float* Kg = K + (size_t)kb * BKT * KVDIM + kvh * HD;
        const float* Vg = V + (size_t)kb * BKT * KVDIM + kvh * HD;
#pragma unroll
        for (int it = 0; it < 8; it++) {
            int i = tid + it * 256;
            int r = i >> 5, g = i & 31;
            *(float4*)&Ks[kswz(r, g)]     = *(const float4*)(Kg + (size_t)r * KVDIM + g * 4);
            *(float4*)&Vs[r * HD + g * 4] = *(const float4*)(Vg + (size_t)r * KVDIM + g * 4);
        }
        __syncthreads();

        float s[8][4];
#pragma unroll
        for (int i = 0; i < 8; i++)
#pragma unroll
            for (int j = 0; j < 4; j++) s[i][j] = 0.f;

#pragma unroll 4
        for (int g = 0; g < 32; g++) {
            float4 kv[4];
#pragma unroll
            for (int j = 0; j < 4; j++)
                kv[j] = *(const float4*)&Ks[kswz(tx*4 + j, g)];
#pragma unroll
            for (int i = 0; i < 8; i++) {
                float4 qv = *(const float4*)&Qs[(ty*8 + i) * HD + g*4];
#pragma unroll
                for (int j = 0; j < 4; j++)
                    s[i][j] += qv.x*kv[j].x + qv.y*kv[j].y
                             + qv.z*kv[j].z + qv.w*kv[j].w;
            }
        }

        const bool diag = (kb >= 2 * qb);
#pragma unroll
        for (int i = 0; i < 8; i++)
#pragma unroll
            for (int j = 0; j < 4; j++) s[i][j] *= scale;
        if (diag) {
            const int roff = qb * BQ + ty * 8;
            const int coff = kb * BKT + tx * 4;
#pragma unroll
            for (int i = 0; i < 8; i++)
#pragma unroll
                for (int j = 0; j < 4; j++)
                    if (coff + j > roff + i) s[i][j] = -1e30f;
        }

#pragma unroll
        for (int i = 0; i < 8; i++) {
            float rm = fmaxf(fmaxf(s[i][0], s[i][1]), fmaxf(s[i][2], s[i][3]));
#pragma unroll
            for (int o = 8; o > 0; o >>= 1)
                rm = fmaxf(rm, __shfl_xor_sync(0xffffffffu, rm, o, 16));
            const float mn    = fmaxf(m[i], rm);
            const float alpha = __expf(m[i] - mn);
            float rs = 0.f;
#pragma unroll
            for (int j = 0; j < 4; j++) { s[i][j] = __expf(s[i][j] - mn); rs += s[i][j]; }
#pragma unroll
            for (int o = 8; o > 0; o >>= 1)
                rs += __shfl_xor_sync(0xffffffffu, rs, o, 16);
            l[i] = l[i] * alpha + rs;
            m[i] = mn;
#pragma unroll
            for (int j = 0; j < 8; j++) acc[i][j] *= alpha;
#pragma unroll
            for (int j = 0; j < 4; j++)
                Ps[(ty*8 + i) * PSTRIDE + tx*4 + j] = s[i][j];
        }
        __syncthreads();

#pragma unroll 4
        for (int kk = 0; kk < BKT; kk++) {
            float4 v0 = *(const float4*)&Vs[kk * HD + tx*8];
            float4 v1 = *(const float4*)&Vs[kk * HD + tx*8 + 4];
#pragma unroll
            for (int i = 0; i < 8; i++) {
                const float p = Ps[(ty*8 + i) * PSTRIDE + kk];
                acc[i][0] += p*v0.x; acc[i][1] += p*v0.y;
                acc[i][2] += p*v0.z; acc[i][3] += p*v0.w;
                acc[i][4] += p*v1.x; acc[i][5] += p*v1.y;
                acc[i][6] += p*v1.z; acc[i][7] += p*v1.w;
            }
        }
    }

    // ---- epilogue: split O into bf16 planes for the out-projection ----
#pragma unroll
    for (int i = 0; i < 8; i++) {
        const float inv = 1.0f / l[i];
        const int row = qb * BQ + ty*8 + i;
        const size_t base = ((size_t)row * DIM + h * HD + tx * 8) >> 1;
#pragma unroll
        for (int q = 0; q < 4; q++) {
            uint32_t hp, lp;
            split_bf16(make_float2(acc[i][2*q] * inv, acc[i][2*q+1] * inv), hp, lp);
            g_Ah[base + q] = hp;
            g_Al[base + q] = lp;
        }
    }
}

// =================================================================
// launch
// =================================================================
#define FLASH_SMEM (((BQ + 2*BKT) * HD + BQ * PSTRIDE) * (int)sizeof(float))

extern "C" void kernel_launch(void* const* d_in, const int* in_sizes, int n_in,
                              void* d_out, int out_size)
{
    const float* x  = (const float*)d_in[0];
    const float* wq = (const float*)d_in[1];
    const float* wk = (const float*)d_in[2];
    const float* wv = (const float*)d_in[3];
    const float* wo = (const float*)d_in[4];
    float* out = (float*)d_out;

    float *Q, *K, *V;
    uint32_t *xh, *xl, *wqh, *wql, *wkh, *wkl, *wvh, *wvl, *woh, *wol;
    cudaGetSymbolAddress((void**)&Q,   g_Q);
    cudaGetSymbolAddress((void**)&K,   g_K);
    cudaGetSymbolAddress((void**)&V,   g_V);
    cudaGetSymbolAddress((void**)&xh,  g_xh);  cudaGetSymbolAddress((void**)&xl,  g_xl);
    cudaGetSymbolAddress((void**)&wqh, g_wqh); cudaGetSymbolAddress((void**)&wql, g_wql);
    cudaGetSymbolAddress((void**)&wkh, g_wkh); cudaGetSymbolAddress((void**)&wkl, g_wkl);
    cudaGetSymbolAddress((void**)&wvh, g_wvh); cudaGetSymbolAddress((void**)&wvl, g_wvl);
    cudaGetSymbolAddress((void**)&woh, g_woh); cudaGetSymbolAddress((void**)&wol, g_wol);

    cudaFuncSetAttribute(gemm_qkv,
                         cudaFuncAttributeMaxDynamicSharedMemorySize, G_SMEM);
    cudaFuncSetAttribute(gemm_out,
                         cudaFuncAttributeMaxDynamicSharedMemorySize, G_SMEM);
    cudaFuncSetAttribute(flash_kernel,
                         cudaFuncAttributeMaxDynamicSharedMemorySize, FLASH_SMEM);

    // RoPE table + one-time input splits (all memory-bound)
    rope_table<<<(SEQ * 64 + 255) / 256, 256>>>();
    {
        const int nx = SEQ * DIM / 2, nq = DIM * DIM / 2, nk = KVDIM * DIM / 2;
        split_plane<<<(nx + 255) / 256, 256>>>((const float2*)x,  xh,  xl,  nx);
        split_plane<<<(nq + 255) / 256, 256>>>((const float2*)wq, wqh, wql, nq);
        split_plane<<<(nk + 255) / 256, 256>>>((const float2*)wk, wkh, wkl, nk);
        split_plane<<<(nk + 255) / 256, 256>>>((const float2*)wv, wvh, wvl, nk);
        split_plane<<<(nq + 255) / 256, 256>>>((const float2*)wo, woh, wol, nq);
    }

    // fused Q/K/V projections (3xBF16 on pre-split planes)
    gemm_qkv<<<dim3(48, SEQ/128), 256, G_SMEM>>>();

    // RoPE apply (Q + K fused)
    rope_apply<<<(ROPE_TOTQ + ROPE_TOTK + 255) / 256, 256>>>(Q, K);

    // attention (BQ=128; writes O as bf16 planes)
    flash_kernel<<<dim3(SEQ/BQ, NH), 256, FLASH_SMEM>>>(Q, K, V);

    // output projection
    gemm_out<<<dim3(DIM/128, SEQ/128), 256, G_SMEM>>>(out);
}